// round 5
// baseline (speedup 1.0000x reference)
#include <cuda_runtime.h>
#include <math.h>

#define Bq   4096
#define Nn   10
#define DIN  32
#define Dd   128
#define PHId 256
#define RHOd 128
#define Ll   3
#define EPS  1e-5f
#define RP   12          // padded row length (floats) for transposed tiles

typedef unsigned long long u64;

__device__ __forceinline__ u64 pk2(float lo, float hi) {
    u64 r; asm("mov.b64 %0,{%1,%2};" : "=l"(r) : "f"(lo), "f"(hi)); return r;
}
__device__ __forceinline__ void upk2(float& lo, float& hi, u64 v) {
    asm("mov.b64 {%0,%1},%2;" : "=f"(lo), "=f"(hi) : "l"(v));
}
__device__ __forceinline__ u64 fma2(u64 a, u64 b, u64 c) {
    u64 d; asm("fma.rn.f32x2 %0,%1,%2,%3;" : "=l"(d) : "l"(a), "l"(b), "l"(c)); return d;
}
__device__ __forceinline__ void ldp10(const float* __restrict__ r, u64* p) {
    ulonglong2 a = *(const ulonglong2*)r;
    ulonglong2 b = *(const ulonglong2*)(r + 4);
    p[0] = a.x; p[1] = a.y; p[2] = b.x; p[3] = b.y;
    p[4] = *(const u64*)(r + 8);
}
__device__ __forceinline__ void stp10(float* __restrict__ r, const float* v) {
    *(float4*)r       = make_float4(v[0], v[1], v[2], v[3]);
    *(float4*)(r + 4) = make_float4(v[4], v[5], v[6], v[7]);
    *(float2*)(r + 8) = make_float2(v[8], v[9]);
}
__device__ __forceinline__ void upk10(float* v, const u64* p) {
    #pragma unroll
    for (int q = 0; q < 5; ++q) upk2(v[2*q], v[2*q+1], p[q]);
}

// shared pool layout (floats); rows are 48B -> 16B aligned
#define HT_OFF   0                    // sHt  [128][12]
#define AG_OFF   (128*RP)             // sAgg [128][12]
#define TT_OFF   (2*128*RP)           // sTt  [128][12]
#define M0_OFF   (3*128*RP)           // sM0  [128][12]
#define M1_OFF   (4*128*RP)           // sM1  [128][12]
#define POOL_SZ  (5*128*RP)
#define PHI_OFF  M0_OFF               // sPhi [256][12] (aliases M0+M1)

__global__ __launch_bounds__(64)
void gcn_deepset_kernel(
    const float* __restrict__ A, const float* __restrict__ X,
    const int* __restrict__ home,
    const float* __restrict__ We1, const float* __restrict__ be1,
    const float* __restrict__ We2, const float* __restrict__ be2,
    const float* __restrict__ rgcn_w, const float* __restrict__ rgcn_root,
    const float* __restrict__ rgcn_b,
    const float* __restrict__ l1w, const float* __restrict__ l1b,
    const float* __restrict__ l2w, const float* __restrict__ l2b,
    const float* __restrict__ ln_g, const float* __restrict__ ln_b,
    const float* __restrict__ p1w, const float* __restrict__ p1b,
    const float* __restrict__ p2w, const float* __restrict__ p2b,
    const float* __restrict__ r1w, const float* __restrict__ r1b,
    const float* __restrict__ r2w, const float* __restrict__ r2b,
    float* __restrict__ out)
{
    __shared__ __align__(16) float pool[POOL_SZ];
    __shared__ __align__(16) float sAbs[Nn * RP];
    __shared__ __align__(16) float2 sCoef[Nn * RP];
    __shared__ float sRawA[Nn * Nn];
    __shared__ __align__(16) float sHS[PHId];
    __shared__ __align__(16) float sAWS[PHId];
    __shared__ float sMu[Nn], sRstd[Nn], shm[Nn], sRed[4];

    const int b    = blockIdx.x;
    const int tid  = threadIdx.x;        // 0..63
    const int lane = tid & 31;
    const int wid  = tid >> 5;
    const int c0   = tid * 2;            // this thread's 2 output columns: c0, c0+1
    const int c4   = tid * 4;            // 4 columns in PHI stages

    // ---- load per-batch inputs ----
    #pragma unroll
    for (int idx = tid; idx < Nn * Nn; idx += 64) {
        float v = A[b * Nn * Nn + idx];
        sRawA[idx] = v;
        sAbs[(idx / Nn) * RP + (idx % Nn)] = fabsf(v);
    }
    for (int idx = tid; idx < Nn * DIN; idx += 64) {   // X transposed into M0
        int i = idx / DIN, k = idx % DIN;
        pool[M0_OFF + k * RP + i] = X[b * Nn * DIN + idx];
    }
    if (tid < Nn) shm[tid] = (float)home[b * Nn + tid];
    __syncthreads();

    // layer-invariant relation coefficients
    if (tid < Nn) {
        int j = tid, c1 = 0;
        #pragma unroll
        for (int i = 0; i < Nn; ++i) c1 += (sRawA[i * Nn + j] > 0.f);
        float r1c = 1.f / fmaxf((float)c1, 1.f);
        float r0c = 1.f / fmaxf((float)(Nn - c1), 1.f);
        #pragma unroll
        for (int i = 0; i < Nn; ++i) {
            bool m1 = sRawA[i * Nn + j] > 0.f;
            sCoef[j * RP + i] = make_float2(m1 ? 0.f : r0c, m1 ? r1c : 0.f);
        }
    }

    const float2 gv = *(const float2*)&ln_g[c0];
    const float2 bv = *(const float2*)&ln_b[c0];

    float h[2][Nn], aggR[2][Nn], v10[Nn];
    u64 acc[2][5];

    // ---- embed stage 1: relu(X@We1+be1) -> TT ----
    {
        float2 bb = *(const float2*)&be1[c0];
        #pragma unroll
        for (int q = 0; q < 5; ++q) { acc[0][q] = pk2(bb.x, bb.x); acc[1][q] = pk2(bb.y, bb.y); }
        const float* W = We1 + c0;
        #pragma unroll 4
        for (int k = 0; k < DIN; ++k) {
            float2 w2 = *(const float2*)&W[k * Dd];
            u64 wp0 = pk2(w2.x, w2.x), wp1 = pk2(w2.y, w2.y), xp[5];
            ldp10(&pool[M0_OFF + k * RP], xp);
            #pragma unroll
            for (int q = 0; q < 5; ++q) {
                acc[0][q] = fma2(xp[q], wp0, acc[0][q]);
                acc[1][q] = fma2(xp[q], wp1, acc[1][q]);
            }
        }
        #pragma unroll
        for (int cc = 0; cc < 2; ++cc) {
            upk10(v10, acc[cc]);
            #pragma unroll
            for (int i = 0; i < Nn; ++i) v10[i] = fmaxf(v10[i], 0.f);
            stp10(&pool[TT_OFF + (c0 + cc) * RP], v10);
        }
    }
    __syncthreads();

    // ---- embed stage 2: (T@We2+be2) -> h ----
    {
        float2 bb = *(const float2*)&be2[c0];
        #pragma unroll
        for (int q = 0; q < 5; ++q) { acc[0][q] = pk2(bb.x, bb.x); acc[1][q] = pk2(bb.y, bb.y); }
        const float* W = We2 + c0;
        #pragma unroll 2
        for (int k = 0; k < Dd; ++k) {
            float2 w2 = *(const float2*)&W[k * Dd];
            u64 wp0 = pk2(w2.x, w2.x), wp1 = pk2(w2.y, w2.y), xp[5];
            ldp10(&pool[TT_OFF + k * RP], xp);
            #pragma unroll
            for (int q = 0; q < 5; ++q) {
                acc[0][q] = fma2(xp[q], wp0, acc[0][q]);
                acc[1][q] = fma2(xp[q], wp1, acc[1][q]);
            }
        }
        upk10(h[0], acc[0]);
        upk10(h[1], acc[1]);
        #pragma unroll
        for (int i = 0; i < Nn; ++i) { aggR[0][i] = 0.f; aggR[1][i] = 0.f; }
    }
    __syncthreads();

    // ---- GNN layers ----
    for (int l = 0; l < Ll; ++l) {
        // residual + publish H
        #pragma unroll
        for (int cc = 0; cc < 2; ++cc) {
            #pragma unroll
            for (int i = 0; i < Nn; ++i) h[cc][i] += aggR[cc][i];
            stp10(&pool[HT_OFF + (c0 + cc) * RP], h[cc]);
        }

        // per-relation means, publish M0/M1
        #pragma unroll
        for (int cc = 0; cc < 2; ++cc) {
            u64 hp[Nn];
            #pragma unroll
            for (int i = 0; i < Nn; ++i) hp[i] = pk2(h[cc][i], h[cc][i]);
            float m0v[Nn], m1v[Nn];
            #pragma unroll
            for (int j = 0; j < Nn; ++j) {
                u64 mp = pk2(0.f, 0.f);
                const u64* cp = (const u64*)&sCoef[j * RP];
                #pragma unroll
                for (int i = 0; i < Nn; ++i) mp = fma2(cp[i], hp[i], mp);
                upk2(m0v[j], m1v[j], mp);
            }
            stp10(&pool[M0_OFF + (c0 + cc) * RP], m0v);
            stp10(&pool[M1_OFF + (c0 + cc) * RP], m1v);
        }
        __syncthreads();   // A

        // H2 = mean0@W0 + mean1@W1 + H@root + b  (regs)
        {
            const float* W0 = rgcn_w    + (size_t)(l * 2 + 0) * Dd * Dd + c0;
            const float* W1 = rgcn_w    + (size_t)(l * 2 + 1) * Dd * Dd + c0;
            const float* Wr = rgcn_root + (size_t)l * Dd * Dd + c0;
            float2 bb = *(const float2*)&rgcn_b[l * Dd + c0];
            #pragma unroll
            for (int q = 0; q < 5; ++q) { acc[0][q] = pk2(bb.x, bb.x); acc[1][q] = pk2(bb.y, bb.y); }
            #pragma unroll 2
            for (int k = 0; k < Dd; ++k) {
                float2 w0 = *(const float2*)&W0[k * Dd];
                float2 w1 = *(const float2*)&W1[k * Dd];
                float2 wr = *(const float2*)&Wr[k * Dd];
                u64 p0[5], p1[5], ph[5];
                ldp10(&pool[M0_OFF + k * RP], p0);
                ldp10(&pool[M1_OFF + k * RP], p1);
                ldp10(&pool[HT_OFF + k * RP], ph);
                u64 a0 = pk2(w0.x, w0.x), a1 = pk2(w1.x, w1.x), ar = pk2(wr.x, wr.x);
                u64 b0 = pk2(w0.y, w0.y), b1 = pk2(w1.y, w1.y), br = pk2(wr.y, wr.y);
                #pragma unroll
                for (int q = 0; q < 5; ++q) {
                    acc[0][q] = fma2(p0[q], a0, fma2(p1[q], a1, fma2(ph[q], ar, acc[0][q])));
                    acc[1][q] = fma2(p0[q], b0, fma2(p1[q], b1, fma2(ph[q], br, acc[1][q])));
                }
            }
        }

        // agg[i] = sum_j H2[j] * |A[i][j]|
        #pragma unroll
        for (int i = 0; i < Nn; ++i) {
            u64 aa[5];
            ldp10(&sAbs[i * RP], aa);
            #pragma unroll
            for (int cc = 0; cc < 2; ++cc) {
                u64 ap = pk2(0.f, 0.f);
                #pragma unroll
                for (int q = 0; q < 5; ++q) ap = fma2(acc[cc][q], aa[q], ap);
                float lo, hi; upk2(lo, hi, ap);
                aggR[cc][i] = lo + hi;
            }
        }
        stp10(&pool[AG_OFF + c0 * RP], aggR[0]);
        stp10(&pool[AG_OFF + (c0 + 1) * RP], aggR[1]);
        __syncthreads();   // B

        // LN stats: warp w handles rows w, w+2, ...
        for (int r = wid; r < Nn; r += 2) {
            float s = 0.f, q = 0.f;
            #pragma unroll
            for (int u = 0; u < 4; ++u) {
                float x = pool[AG_OFF + (lane + 32 * u) * RP + r];
                s += x; q += x * x;
            }
            #pragma unroll
            for (int o = 16; o > 0; o >>= 1) {
                s += __shfl_xor_sync(0xffffffffu, s, o);
                q += __shfl_xor_sync(0xffffffffu, q, o);
            }
            if (lane == 0) {
                float mu = s * (1.f / Dd);
                float var = q * (1.f / Dd) - mu * mu;
                sMu[r] = mu; sRstd[r] = rsqrtf(var + EPS);
            }
        }
        __syncthreads();   // C

        // normalize + relu, publish
        #pragma unroll
        for (int i = 0; i < Nn; ++i) {
            float rs = sRstd[i], mu = sMu[i];
            aggR[0][i] = fmaxf((aggR[0][i] - mu) * rs * gv.x + bv.x, 0.f);
            aggR[1][i] = fmaxf((aggR[1][i] - mu) * rs * gv.y + bv.y, 0.f);
        }
        stp10(&pool[AG_OFF + c0 * RP], aggR[0]);
        stp10(&pool[AG_OFF + (c0 + 1) * RP], aggR[1]);
        __syncthreads();   // D

        // l1: relu(agg@W+b) -> TT
        {
            const float* W = l1w + (size_t)l * Dd * Dd + c0;
            float2 bb = *(const float2*)&l1b[l * Dd + c0];
            #pragma unroll
            for (int q = 0; q < 5; ++q) { acc[0][q] = pk2(bb.x, bb.x); acc[1][q] = pk2(bb.y, bb.y); }
            #pragma unroll 2
            for (int k = 0; k < Dd; ++k) {
                float2 w2 = *(const float2*)&W[k * Dd];
                u64 wp0 = pk2(w2.x, w2.x), wp1 = pk2(w2.y, w2.y), xp[5];
                ldp10(&pool[AG_OFF + k * RP], xp);
                #pragma unroll
                for (int q = 0; q < 5; ++q) {
                    acc[0][q] = fma2(xp[q], wp0, acc[0][q]);
                    acc[1][q] = fma2(xp[q], wp1, acc[1][q]);
                }
            }
            __syncthreads();
            #pragma unroll
            for (int cc = 0; cc < 2; ++cc) {
                upk10(v10, acc[cc]);
                #pragma unroll
                for (int i = 0; i < Nn; ++i) v10[i] = fmaxf(v10[i], 0.f);
                stp10(&pool[TT_OFF + (c0 + cc) * RP], v10);
            }
        }
        __syncthreads();   // E

        // l2: (t@W+b) -> aggR
        {
            const float* W = l2w + (size_t)l * Dd * Dd + c0;
            float2 bb = *(const float2*)&l2b[l * Dd + c0];
            #pragma unroll
            for (int q = 0; q < 5; ++q) { acc[0][q] = pk2(bb.x, bb.x); acc[1][q] = pk2(bb.y, bb.y); }
            #pragma unroll 2
            for (int k = 0; k < Dd; ++k) {
                float2 w2 = *(const float2*)&W[k * Dd];
                u64 wp0 = pk2(w2.x, w2.x), wp1 = pk2(w2.y, w2.y), xp[5];
                ldp10(&pool[TT_OFF + k * RP], xp);
                #pragma unroll
                for (int q = 0; q < 5; ++q) {
                    acc[0][q] = fma2(xp[q], wp0, acc[0][q]);
                    acc[1][q] = fma2(xp[q], wp1, acc[1][q]);
                }
            }
            upk10(aggR[0], acc[0]);
            upk10(aggR[1], acc[1]);
        }
    }

    // ---- final residual, publish H ----
    #pragma unroll
    for (int cc = 0; cc < 2; ++cc) {
        #pragma unroll
        for (int i = 0; i < Nn; ++i) h[cc][i] += aggR[cc][i];
        stp10(&pool[HT_OFF + (c0 + cc) * RP], h[cc]);
    }
    __syncthreads();

    // ---- phi1: relu(H@p1w+p1b), 4 columns c4..c4+3 -> PHI region ----
    {
        float4 bb = *(const float4*)&p1b[c4];
        u64 a0[5], a1[5], a2[5], a3[5];
        #pragma unroll
        for (int q = 0; q < 5; ++q) {
            a0[q] = pk2(bb.x, bb.x); a1[q] = pk2(bb.y, bb.y);
            a2[q] = pk2(bb.z, bb.z); a3[q] = pk2(bb.w, bb.w);
        }
        const float* W = p1w + c4;
        #pragma unroll 2
        for (int k = 0; k < Dd; ++k) {
            float4 w4 = *(const float4*)&W[k * PHId];
            u64 w0 = pk2(w4.x, w4.x), w1 = pk2(w4.y, w4.y);
            u64 w2 = pk2(w4.z, w4.z), w3 = pk2(w4.w, w4.w), xp[5];
            ldp10(&pool[HT_OFF + k * RP], xp);
            #pragma unroll
            for (int q = 0; q < 5; ++q) {
                a0[q] = fma2(xp[q], w0, a0[q]);
                a1[q] = fma2(xp[q], w1, a1[q]);
                a2[q] = fma2(xp[q], w2, a2[q]);
                a3[q] = fma2(xp[q], w3, a3[q]);
            }
        }
        __syncthreads();   // done reading HT/M-regions before overwriting PHI alias
        u64* regs[4] = {a0, a1, a2, a3};
        #pragma unroll
        for (int cc = 0; cc < 4; ++cc) {
            upk10(v10, regs[cc]);
            #pragma unroll
            for (int i = 0; i < Nn; ++i) v10[i] = fmaxf(v10[i], 0.f);
            stp10(&pool[PHI_OFF + (c4 + cc) * RP], v10);
        }
    }
    __syncthreads();

    // ---- phi2 + masked sums ----
    {
        float4 bb = *(const float4*)&p2b[c4];
        u64 a0[5], a1[5], a2[5], a3[5];
        #pragma unroll
        for (int q = 0; q < 5; ++q) {
            a0[q] = pk2(bb.x, bb.x); a1[q] = pk2(bb.y, bb.y);
            a2[q] = pk2(bb.z, bb.z); a3[q] = pk2(bb.w, bb.w);
        }
        const float* W = p2w + c4;
        #pragma unroll 2
        for (int k = 0; k < PHId; ++k) {
            float4 w4 = *(const float4*)&W[k * PHId];
            u64 w0 = pk2(w4.x, w4.x), w1 = pk2(w4.y, w4.y);
            u64 w2 = pk2(w4.z, w4.z), w3 = pk2(w4.w, w4.w), xp[5];
            ldp10(&pool[PHI_OFF + k * RP], xp);
            #pragma unroll
            for (int q = 0; q < 5; ++q) {
                a0[q] = fma2(xp[q], w0, a0[q]);
                a1[q] = fma2(xp[q], w1, a1[q]);
                a2[q] = fma2(xp[q], w2, a2[q]);
                a3[q] = fma2(xp[q], w3, a3[q]);
            }
        }
        u64* regs[4] = {a0, a1, a2, a3};
        float hs[4], as[4];
        #pragma unroll
        for (int cc = 0; cc < 4; ++cc) {
            upk10(v10, regs[cc]);
            float hsv = 0.f, asv = 0.f;
            #pragma unroll
            for (int i = 0; i < Nn; ++i) {
                float u = fmaxf(v10[i], 0.f);
                float m = shm[i];
                hsv += u * m; asv += u * (1.f - m);
            }
            hs[cc] = hsv; as[cc] = asv;
        }
        *(float4*)&sHS[c4]  = make_float4(hs[0], hs[1], hs[2], hs[3]);
        *(float4*)&sAWS[c4] = make_float4(as[0], as[1], as[2], as[3]);
    }
    __syncthreads();

    // ---- rho(hs) - rho(aws): 2 columns per thread ----
    {
        float2 rb = *(const float2*)&r1b[c0];
        float acch0 = rb.x, acch1 = rb.y, acca0 = rb.x, acca1 = rb.y;
        const float* W = r1w + c0;
        #pragma unroll 2
        for (int k = 0; k < PHId; k += 4) {
            float4 hv = *(const float4*)&sHS[k];
            float4 av = *(const float4*)&sAWS[k];
            float2 wA = *(const float2*)&W[(k + 0) * RHOd];
            float2 wB = *(const float2*)&W[(k + 1) * RHOd];
            float2 wC = *(const float2*)&W[(k + 2) * RHOd];
            float2 wD = *(const float2*)&W[(k + 3) * RHOd];
            acch0 += hv.x * wA.x + hv.y * wB.x + hv.z * wC.x + hv.w * wD.x;
            acch1 += hv.x * wA.y + hv.y * wB.y + hv.z * wC.y + hv.w * wD.y;
            acca0 += av.x * wA.x + av.y * wB.x + av.z * wC.x + av.w * wD.x;
            acca1 += av.x * wA.y + av.y * wB.y + av.z * wC.y + av.w * wD.y;
        }
        float2 w2v = *(const float2*)&r2w[c0];
        float ph = fmaxf(acch0, 0.f) * w2v.x + fmaxf(acch1, 0.f) * w2v.y;
        float pa = fmaxf(acca0, 0.f) * w2v.x + fmaxf(acca1, 0.f) * w2v.y;
        #pragma unroll
        for (int o = 16; o > 0; o >>= 1) {
            ph += __shfl_down_sync(0xffffffffu, ph, o);
            pa += __shfl_down_sync(0xffffffffu, pa, o);
        }
        if (lane == 0) { sRed[wid] = ph; sRed[2 + wid] = pa; }
        __syncthreads();
        if (tid == 0) {
            float dh = sRed[0] + sRed[1];
            float da = sRed[2] + sRed[3];
            out[b] = 0.5f + 0.5f * tanhf(dh - da);
        }
    }
}

extern "C" void kernel_launch(void* const* d_in, const int* in_sizes, int n_in,
                              void* d_out, int out_size)
{
    const float* A    = (const float*)d_in[0];
    const float* X    = (const float*)d_in[1];
    const int*   home = (const int*)  d_in[2];
    const float* We1  = (const float*)d_in[3];
    const float* be1  = (const float*)d_in[4];
    const float* We2  = (const float*)d_in[5];
    const float* be2  = (const float*)d_in[6];
    const float* rgw  = (const float*)d_in[7];
    const float* rgr  = (const float*)d_in[8];
    const float* rgb  = (const float*)d_in[9];
    const float* l1w  = (const float*)d_in[10];
    const float* l1b  = (const float*)d_in[11];
    const float* l2w  = (const float*)d_in[12];
    const float* l2b  = (const float*)d_in[13];
    const float* lng  = (const float*)d_in[14];
    const float* lnb  = (const float*)d_in[15];
    const float* p1w  = (const float*)d_in[16];
    const float* p1b  = (const float*)d_in[17];
    const float* p2w  = (const float*)d_in[18];
    const float* p2b  = (const float*)d_in[19];
    const float* r1w  = (const float*)d_in[20];
    const float* r1b  = (const float*)d_in[21];
    const float* r2w  = (const float*)d_in[22];
    const float* r2b  = (const float*)d_in[23];

    gcn_deepset_kernel<<<Bq, 64>>>(
        A, X, home, We1, be1, We2, be2, rgw, rgr, rgb,
        l1w, l1b, l2w, l2b, lng, lnb, p1w, p1b, p2w, p2b,
        r1w, r1b, r2w, r2b, (float*)d_out);
    (void)in_sizes; (void)n_in; (void)out_size; (void)r2b;
}

// round 6
// speedup vs baseline: 1.5414x; 1.5414x over previous
#include <cuda_runtime.h>
#include <math.h>

#define Bq   4096
#define Nn   10
#define DIN  32
#define Dd   128
#define PHId 256
#define RHOd 128
#define Ll   3
#define EPS  1e-5f
#define RP   12

typedef unsigned long long u64;

__device__ __forceinline__ u64 pk2(float lo, float hi) {
    u64 r; asm("mov.b64 %0,{%1,%2};" : "=l"(r) : "f"(lo), "f"(hi)); return r;
}
__device__ __forceinline__ void upk2(float& lo, float& hi, u64 v) {
    asm("mov.b64 {%0,%1},%2;" : "=f"(lo), "=f"(hi) : "l"(v));
}
__device__ __forceinline__ u64 fma2(u64 a, u64 b, u64 c) {
    u64 d; asm("fma.rn.f32x2 %0,%1,%2,%3;" : "=l"(d) : "l"(a), "l"(b), "l"(c)); return d;
}
__device__ __forceinline__ void ldp10(const float* __restrict__ r, u64* p) {
    ulonglong2 a = *(const ulonglong2*)r;
    ulonglong2 b = *(const ulonglong2*)(r + 4);
    p[0] = a.x; p[1] = a.y; p[2] = b.x; p[3] = b.y;
    p[4] = *(const u64*)(r + 8);
}
__device__ __forceinline__ void ldf10(const float* __restrict__ r, float* v) {
    float4 a = *(const float4*)r; float4 b = *(const float4*)(r + 4);
    float2 c = *(const float2*)(r + 8);
    v[0]=a.x; v[1]=a.y; v[2]=a.z; v[3]=a.w;
    v[4]=b.x; v[5]=b.y; v[6]=b.z; v[7]=b.w;
    v[8]=c.x; v[9]=c.y;
}
__device__ __forceinline__ void stp10(float* __restrict__ r, const float* v) {
    *(float4*)r       = make_float4(v[0], v[1], v[2], v[3]);
    *(float4*)(r + 4) = make_float4(v[4], v[5], v[6], v[7]);
    *(float2*)(r + 8) = make_float2(v[8], v[9]);
}
__device__ __forceinline__ void upk10(float* v, const u64* p) {
    #pragma unroll
    for (int q = 0; q < 5; ++q) upk2(v[2*q], v[2*q+1], p[q]);
}

// shared pool: HT [0,128RP), AG [128RP,256RP), TT [256RP,384RP)
// PHI [256][RP] aliases AG+TT (contiguous)
#define HT_OFF   0
#define AG_OFF   (128*RP)
#define TT_OFF   (2*128*RP)
#define POOL_SZ  (3*128*RP)
#define PHI_OFF  AG_OFF

__global__ __launch_bounds__(64)
void gcn_deepset_kernel(
    const float* __restrict__ A, const float* __restrict__ X,
    const int* __restrict__ home,
    const float* __restrict__ We1, const float* __restrict__ be1,
    const float* __restrict__ We2, const float* __restrict__ be2,
    const float* __restrict__ rgcn_w, const float* __restrict__ rgcn_root,
    const float* __restrict__ rgcn_b,
    const float* __restrict__ l1w, const float* __restrict__ l1b,
    const float* __restrict__ l2w, const float* __restrict__ l2b,
    const float* __restrict__ ln_g, const float* __restrict__ ln_b,
    const float* __restrict__ p1w, const float* __restrict__ p1b,
    const float* __restrict__ p2w, const float* __restrict__ p2b,
    const float* __restrict__ r1w, const float* __restrict__ r1b,
    const float* __restrict__ r2w, const float* __restrict__ r2b,
    float* __restrict__ out)
{
    __shared__ __align__(16) float pool[POOL_SZ];
    __shared__ __align__(16) float sAbs[Nn * RP];   // |A| rows (i), packed along j
    __shared__ __align__(16) float sC0[Nn * RP];    // coef0[i][j], packed along j
    __shared__ __align__(16) float sC1[Nn * RP];    // coef1[i][j]
    __shared__ float sRawA[Nn * Nn];
    __shared__ __align__(16) float sHS[PHId];
    __shared__ __align__(16) float sAWS[PHId];
    __shared__ float sMu[Nn], sRstd[Nn], shm[Nn], sRed[4];

    const int b    = blockIdx.x;
    const int tid  = threadIdx.x;        // 0..63
    const int lane = tid & 31;
    const int wid  = tid >> 5;
    const int c0   = tid * 2;
    const int c4   = tid * 4;

    // ---- load per-batch inputs ----
    #pragma unroll
    for (int idx = tid; idx < Nn * Nn; idx += 64) {
        float v = A[b * Nn * Nn + idx];
        sRawA[idx] = v;
        sAbs[(idx / Nn) * RP + (idx % Nn)] = fabsf(v);
    }
    for (int idx = tid; idx < Nn * DIN; idx += 64) {   // X^T into AG region
        int i = idx / DIN, k = idx % DIN;
        pool[AG_OFF + k * RP + i] = X[b * Nn * DIN + idx];
    }
    if (tid < Nn) shm[tid] = (float)home[b * Nn + tid];
    __syncthreads();

    // layer-invariant relation coefficients, stored row=source i, packed along j
    if (tid < Nn) {
        int j = tid, c1 = 0;
        #pragma unroll
        for (int i = 0; i < Nn; ++i) c1 += (sRawA[i * Nn + j] > 0.f);
        float r1c = 1.f / fmaxf((float)c1, 1.f);
        float r0c = 1.f / fmaxf((float)(Nn - c1), 1.f);
        #pragma unroll
        for (int i = 0; i < Nn; ++i) {
            bool m1 = sRawA[i * Nn + j] > 0.f;
            sC0[i * RP + j] = m1 ? 0.f : r0c;
            sC1[i * RP + j] = m1 ? r1c : 0.f;
        }
    }

    const float2 gv = *(const float2*)&ln_g[c0];
    const float2 bv = *(const float2*)&ln_b[c0];

    float aggR[2][Nn], v10[Nn];
    u64 acc[2][5];

    // ---- embed1: relu(X@We1+be1) -> TT ----
    {
        float2 bb = *(const float2*)&be1[c0];
        #pragma unroll
        for (int q = 0; q < 5; ++q) { acc[0][q] = pk2(bb.x, bb.x); acc[1][q] = pk2(bb.y, bb.y); }
        const float* W = We1 + c0;
        #pragma unroll 8
        for (int k = 0; k < DIN; ++k) {
            float2 w2 = *(const float2*)&W[k * Dd];
            u64 wp0 = pk2(w2.x, w2.x), wp1 = pk2(w2.y, w2.y), xp[5];
            ldp10(&pool[AG_OFF + k * RP], xp);
            #pragma unroll
            for (int q = 0; q < 5; ++q) {
                acc[0][q] = fma2(xp[q], wp0, acc[0][q]);
                acc[1][q] = fma2(xp[q], wp1, acc[1][q]);
            }
        }
        #pragma unroll
        for (int cc = 0; cc < 2; ++cc) {
            upk10(v10, acc[cc]);
            #pragma unroll
            for (int i = 0; i < Nn; ++i) v10[i] = fmaxf(v10[i], 0.f);
            stp10(&pool[TT_OFF + (c0 + cc) * RP], v10);
        }
    }
    __syncthreads();

    // ---- embed2: (T@We2+be2) -> HT ----
    {
        float2 bb = *(const float2*)&be2[c0];
        #pragma unroll
        for (int q = 0; q < 5; ++q) { acc[0][q] = pk2(bb.x, bb.x); acc[1][q] = pk2(bb.y, bb.y); }
        const float* W = We2 + c0;
        #pragma unroll 8
        for (int k = 0; k < Dd; ++k) {
            float2 w2 = *(const float2*)&W[k * Dd];
            u64 wp0 = pk2(w2.x, w2.x), wp1 = pk2(w2.y, w2.y), xp[5];
            ldp10(&pool[TT_OFF + k * RP], xp);
            #pragma unroll
            for (int q = 0; q < 5; ++q) {
                acc[0][q] = fma2(xp[q], wp0, acc[0][q]);
                acc[1][q] = fma2(xp[q], wp1, acc[1][q]);
            }
        }
        #pragma unroll
        for (int cc = 0; cc < 2; ++cc) {
            upk10(v10, acc[cc]);
            stp10(&pool[HT_OFF + (c0 + cc) * RP], v10);
        }
        #pragma unroll
        for (int i = 0; i < Nn; ++i) { aggR[0][i] = 0.f; aggR[1][i] = 0.f; }
    }
    __syncthreads();

    // ---- GNN layers ----
    for (int l = 0; l < Ll; ++l) {
        // residual: HT(own rows) += aggR
        #pragma unroll
        for (int cc = 0; cc < 2; ++cc) {
            ldf10(&pool[HT_OFF + (c0 + cc) * RP], v10);
            #pragma unroll
            for (int i = 0; i < Nn; ++i) v10[i] += aggR[cc][i];
            stp10(&pool[HT_OFF + (c0 + cc) * RP], v10);
        }
        __syncthreads();   // A: full H visible

        // Y0=H@W0, Y1=H@W1, Yr=H@Wr+b  (single pass over HT rows)
        u64 Y0[2][5], Y1[2][5], Yr[2][5];
        {
            const float* W0 = rgcn_w    + (size_t)(l * 2 + 0) * Dd * Dd + c0;
            const float* W1 = rgcn_w    + (size_t)(l * 2 + 1) * Dd * Dd + c0;
            const float* Wr = rgcn_root + (size_t)l * Dd * Dd + c0;
            float2 bb = *(const float2*)&rgcn_b[l * Dd + c0];
            #pragma unroll
            for (int q = 0; q < 5; ++q) {
                Y0[0][q] = 0; Y0[1][q] = 0;
                Y1[0][q] = 0; Y1[1][q] = 0;
                Yr[0][q] = pk2(bb.x, bb.x); Yr[1][q] = pk2(bb.y, bb.y);
            }
            #pragma unroll 4
            for (int k = 0; k < Dd; ++k) {
                float2 w0 = *(const float2*)&W0[k * Dd];
                float2 w1 = *(const float2*)&W1[k * Dd];
                float2 wr = *(const float2*)&Wr[k * Dd];
                u64 xp[5];
                ldp10(&pool[HT_OFF + k * RP], xp);
                u64 a0 = pk2(w0.x, w0.x), b0 = pk2(w0.y, w0.y);
                u64 a1 = pk2(w1.x, w1.x), b1 = pk2(w1.y, w1.y);
                u64 ar = pk2(wr.x, wr.x), br = pk2(wr.y, wr.y);
                #pragma unroll
                for (int q = 0; q < 5; ++q) {
                    Y0[0][q] = fma2(xp[q], a0, Y0[0][q]);
                    Y0[1][q] = fma2(xp[q], b0, Y0[1][q]);
                    Y1[0][q] = fma2(xp[q], a1, Y1[0][q]);
                    Y1[1][q] = fma2(xp[q], b1, Y1[1][q]);
                    Yr[0][q] = fma2(xp[q], ar, Yr[0][q]);
                    Yr[1][q] = fma2(xp[q], br, Yr[1][q]);
                }
            }
        }

        // node-mix: H2 = Yr + C0^T.Y0 + C1^T.Y1   (pairs over target j, in Yr)
        {
            float y0s[2][Nn], y1s[2][Nn];
            upk10(y0s[0], Y0[0]); upk10(y0s[1], Y0[1]);
            upk10(y1s[0], Y1[0]); upk10(y1s[1], Y1[1]);
            #pragma unroll
            for (int i = 0; i < Nn; ++i) {
                u64 c0p[5], c1p[5];
                #pragma unroll
                for (int q = 0; q < 5; ++q) {
                    c0p[q] = *(const u64*)&sC0[i * RP + 2*q];
                    c1p[q] = *(const u64*)&sC1[i * RP + 2*q];
                }
                #pragma unroll
                for (int cc = 0; cc < 2; ++cc) {
                    u64 yb0 = pk2(y0s[cc][i], y0s[cc][i]);
                    u64 yb1 = pk2(y1s[cc][i], y1s[cc][i]);
                    #pragma unroll
                    for (int q = 0; q < 5; ++q)
                        Yr[cc][q] = fma2(c0p[q], yb0, fma2(c1p[q], yb1, Yr[cc][q]));
                }
            }
        }

        // agg[i] = sum_j H2[j] * |A[i][j]|
        #pragma unroll
        for (int i = 0; i < Nn; ++i) {
            u64 aa[5];
            ldp10(&sAbs[i * RP], aa);
            #pragma unroll
            for (int cc = 0; cc < 2; ++cc) {
                u64 ap = pk2(0.f, 0.f);
                #pragma unroll
                for (int q = 0; q < 5; ++q) ap = fma2(Yr[cc][q], aa[q], ap);
                float lo, hi; upk2(lo, hi, ap);
                aggR[cc][i] = lo + hi;
            }
        }
        stp10(&pool[AG_OFF + c0 * RP], aggR[0]);
        stp10(&pool[AG_OFF + (c0 + 1) * RP], aggR[1]);
        __syncthreads();   // B

        // LN stats
        for (int r = wid; r < Nn; r += 2) {
            float s = 0.f, q = 0.f;
            #pragma unroll
            for (int u = 0; u < 4; ++u) {
                float x = pool[AG_OFF + (lane + 32 * u) * RP + r];
                s += x; q += x * x;
            }
            #pragma unroll
            for (int o = 16; o > 0; o >>= 1) {
                s += __shfl_xor_sync(0xffffffffu, s, o);
                q += __shfl_xor_sync(0xffffffffu, q, o);
            }
            if (lane == 0) {
                float mu = s * (1.f / Dd);
                float var = q * (1.f / Dd) - mu * mu;
                sMu[r] = mu; sRstd[r] = rsqrtf(var + EPS);
            }
        }
        __syncthreads();   // C

        // normalize + relu -> AG
        #pragma unroll
        for (int i = 0; i < Nn; ++i) {
            float rs = sRstd[i], mu = sMu[i];
            aggR[0][i] = fmaxf((aggR[0][i] - mu) * rs * gv.x + bv.x, 0.f);
            aggR[1][i] = fmaxf((aggR[1][i] - mu) * rs * gv.y + bv.y, 0.f);
        }
        stp10(&pool[AG_OFF + c0 * RP], aggR[0]);
        stp10(&pool[AG_OFF + (c0 + 1) * RP], aggR[1]);
        __syncthreads();   // D

        // l1: relu(AG@W+b) -> TT
        {
            const float* W = l1w + (size_t)l * Dd * Dd + c0;
            float2 bb = *(const float2*)&l1b[l * Dd + c0];
            #pragma unroll
            for (int q = 0; q < 5; ++q) { acc[0][q] = pk2(bb.x, bb.x); acc[1][q] = pk2(bb.y, bb.y); }
            #pragma unroll 8
            for (int k = 0; k < Dd; ++k) {
                float2 w2 = *(const float2*)&W[k * Dd];
                u64 wp0 = pk2(w2.x, w2.x), wp1 = pk2(w2.y, w2.y), xp[5];
                ldp10(&pool[AG_OFF + k * RP], xp);
                #pragma unroll
                for (int q = 0; q < 5; ++q) {
                    acc[0][q] = fma2(xp[q], wp0, acc[0][q]);
                    acc[1][q] = fma2(xp[q], wp1, acc[1][q]);
                }
            }
            #pragma unroll
            for (int cc = 0; cc < 2; ++cc) {
                upk10(v10, acc[cc]);
                #pragma unroll
                for (int i = 0; i < Nn; ++i) v10[i] = fmaxf(v10[i], 0.f);
                stp10(&pool[TT_OFF + (c0 + cc) * RP], v10);
            }
        }
        __syncthreads();   // E

        // l2: TT@W+b -> aggR
        {
            const float* W = l2w + (size_t)l * Dd * Dd + c0;
            float2 bb = *(const float2*)&l2b[l * Dd + c0];
            #pragma unroll
            for (int q = 0; q < 5; ++q) { acc[0][q] = pk2(bb.x, bb.x); acc[1][q] = pk2(bb.y, bb.y); }
            #pragma unroll 8
            for (int k = 0; k < Dd; ++k) {
                float2 w2 = *(const float2*)&W[k * Dd];
                u64 wp0 = pk2(w2.x, w2.x), wp1 = pk2(w2.y, w2.y), xp[5];
                ldp10(&pool[TT_OFF + k * RP], xp);
                #pragma unroll
                for (int q = 0; q < 5; ++q) {
                    acc[0][q] = fma2(xp[q], wp0, acc[0][q]);
                    acc[1][q] = fma2(xp[q], wp1, acc[1][q]);
                }
            }
            upk10(aggR[0], acc[0]);
            upk10(aggR[1], acc[1]);
        }
    }

    // ---- final residual into HT ----
    #pragma unroll
    for (int cc = 0; cc < 2; ++cc) {
        ldf10(&pool[HT_OFF + (c0 + cc) * RP], v10);
        #pragma unroll
        for (int i = 0; i < Nn; ++i) v10[i] += aggR[cc][i];
        stp10(&pool[HT_OFF + (c0 + cc) * RP], v10);
    }
    __syncthreads();

    // ---- phi1: relu(H@p1w+p1b) -> PHI (4 cols/thread) ----
    {
        float4 bb = *(const float4*)&p1b[c4];
        u64 a0[5], a1[5], a2[5], a3[5];
        #pragma unroll
        for (int q = 0; q < 5; ++q) {
            a0[q] = pk2(bb.x, bb.x); a1[q] = pk2(bb.y, bb.y);
            a2[q] = pk2(bb.z, bb.z); a3[q] = pk2(bb.w, bb.w);
        }
        const float* W = p1w + c4;
        #pragma unroll 4
        for (int k = 0; k < Dd; ++k) {
            float4 w4 = *(const float4*)&W[k * PHId];
            u64 w0 = pk2(w4.x, w4.x), w1 = pk2(w4.y, w4.y);
            u64 w2 = pk2(w4.z, w4.z), w3 = pk2(w4.w, w4.w), xp[5];
            ldp10(&pool[HT_OFF + k * RP], xp);
            #pragma unroll
            for (int q = 0; q < 5; ++q) {
                a0[q] = fma2(xp[q], w0, a0[q]);
                a1[q] = fma2(xp[q], w1, a1[q]);
                a2[q] = fma2(xp[q], w2, a2[q]);
                a3[q] = fma2(xp[q], w3, a3[q]);
            }
        }
        __syncthreads();   // all TT/AG reads done before PHI overwrite
        u64* regs[4] = {a0, a1, a2, a3};
        #pragma unroll
        for (int cc = 0; cc < 4; ++cc) {
            upk10(v10, regs[cc]);
            #pragma unroll
            for (int i = 0; i < Nn; ++i) v10[i] = fmaxf(v10[i], 0.f);
            stp10(&pool[PHI_OFF + (c4 + cc) * RP], v10);
        }
    }
    __syncthreads();

    // ---- phi2 + masked sums ----
    {
        float4 bb = *(const float4*)&p2b[c4];
        u64 a0[5], a1[5], a2[5], a3[5];
        #pragma unroll
        for (int q = 0; q < 5; ++q) {
            a0[q] = pk2(bb.x, bb.x); a1[q] = pk2(bb.y, bb.y);
            a2[q] = pk2(bb.z, bb.z); a3[q] = pk2(bb.w, bb.w);
        }
        const float* W = p2w + c4;
        #pragma unroll 4
        for (int k = 0; k < PHId; ++k) {
            float4 w4 = *(const float4*)&W[k * PHId];
            u64 w0 = pk2(w4.x, w4.x), w1 = pk2(w4.y, w4.y);
            u64 w2 = pk2(w4.z, w4.z), w3 = pk2(w4.w, w4.w), xp[5];
            ldp10(&pool[PHI_OFF + k * RP], xp);
            #pragma unroll
            for (int q = 0; q < 5; ++q) {
                a0[q] = fma2(xp[q], w0, a0[q]);
                a1[q] = fma2(xp[q], w1, a1[q]);
                a2[q] = fma2(xp[q], w2, a2[q]);
                a3[q] = fma2(xp[q], w3, a3[q]);
            }
        }
        u64* regs[4] = {a0, a1, a2, a3};
        float hs[4], as[4];
        #pragma unroll
        for (int cc = 0; cc < 4; ++cc) {
            upk10(v10, regs[cc]);
            float hsv = 0.f, asv = 0.f;
            #pragma unroll
            for (int i = 0; i < Nn; ++i) {
                float u = fmaxf(v10[i], 0.f);
                float m = shm[i];
                hsv += u * m; asv += u * (1.f - m);
            }
            hs[cc] = hsv; as[cc] = asv;
        }
        *(float4*)&sHS[c4]  = make_float4(hs[0], hs[1], hs[2], hs[3]);
        *(float4*)&sAWS[c4] = make_float4(as[0], as[1], as[2], as[3]);
    }
    __syncthreads();

    // ---- rho(hs) - rho(aws) ----
    {
        float2 rb = *(const float2*)&r1b[c0];
        float acch0 = rb.x, acch1 = rb.y, acca0 = rb.x, acca1 = rb.y;
        const float* W = r1w + c0;
        #pragma unroll 4
        for (int k = 0; k < PHId; k += 4) {
            float4 hv = *(const float4*)&sHS[k];
            float4 av = *(const float4*)&sAWS[k];
            float2 wA = *(const float2*)&W[(k + 0) * RHOd];
            float2 wB = *(const float2*)&W[(k + 1) * RHOd];
            float2 wC = *(const float2*)&W[(k + 2) * RHOd];
            float2 wD = *(const float2*)&W[(k + 3) * RHOd];
            acch0 += hv.x * wA.x + hv.y * wB.x + hv.z * wC.x + hv.w * wD.x;
            acch1 += hv.x * wA.y + hv.y * wB.y + hv.z * wC.y + hv.w * wD.y;
            acca0 += av.x * wA.x + av.y * wB.x + av.z * wC.x + av.w * wD.x;
            acca1 += av.x * wA.y + av.y * wB.y + av.z * wC.y + av.w * wD.y;
        }
        float2 w2v = *(const float2*)&r2w[c0];
        float ph = fmaxf(acch0, 0.f) * w2v.x + fmaxf(acch1, 0.f) * w2v.y;
        float pa = fmaxf(acca0, 0.f) * w2v.x + fmaxf(acca1, 0.f) * w2v.y;
        #pragma unroll
        for (int o = 16; o > 0; o >>= 1) {
            ph += __shfl_down_sync(0xffffffffu, ph, o);
            pa += __shfl_down_sync(0xffffffffu, pa, o);
        }
        if (lane == 0) { sRed[wid] = ph; sRed[2 + wid] = pa; }
        __syncthreads();
        if (tid == 0) {
            float dh = sRed[0] + sRed[1];
            float da = sRed[2] + sRed[3];
            out[b] = 0.5f + 0.5f * tanhf(dh - da);
        }
    }
}

extern "C" void kernel_launch(void* const* d_in, const int* in_sizes, int n_in,
                              void* d_out, int out_size)
{
    const float* A    = (const float*)d_in[0];
    const float* X    = (const float*)d_in[1];
    const int*   home = (const int*)  d_in[2];
    const float* We1  = (const float*)d_in[3];
    const float* be1  = (const float*)d_in[4];
    const float* We2  = (const float*)d_in[5];
    const float* be2  = (const float*)d_in[6];
    const float* rgw  = (const float*)d_in[7];
    const float* rgr  = (const float*)d_in[8];
    const float* rgb  = (const float*)d_in[9];
    const float* l1w  = (const float*)d_in[10];
    const float* l1b  = (const float*)d_in[11];
    const float* l2w  = (const float*)d_in[12];
    const float* l2b  = (const float*)d_in[13];
    const float* lng  = (const float*)d_in[14];
    const float* lnb  = (const float*)d_in[15];
    const float* p1w  = (const float*)d_in[16];
    const float* p1b  = (const float*)d_in[17];
    const float* p2w  = (const float*)d_in[18];
    const float* p2b  = (const float*)d_in[19];
    const float* r1w  = (const float*)d_in[20];
    const float* r1b  = (const float*)d_in[21];
    const float* r2w  = (const float*)d_in[22];
    const float* r2b  = (const float*)d_in[23];

    gcn_deepset_kernel<<<Bq, 64>>>(
        A, X, home, We1, be1, We2, be2, rgw, rgr, rgb,
        l1w, l1b, l2w, l2b, lng, lnb, p1w, p1b, p2w, p2b,
        r1w, r1b, r2w, r2b, (float*)d_out);
    (void)in_sizes; (void)n_in; (void)out_size; (void)r2b;
}